// round 16
// baseline (speedup 1.0000x reference)
#include <cuda_runtime.h>
#include <cuda_bf16.h>
#include <cuda_fp16.h>
#include <cstdint>

#define D_IN 1024
#define H_SZ 64
#define M_TOT 8192   // B*T
#define T_SEQ 2048
#define B_SZ 4
#define NSPLIT 6
#define TILES_PER_SPLIT 6
#define QTILES 32            // T_SEQ / 64

// ---------------- global scratch ----------------
__device__ __nv_bfloat16 g_wh[192 * D_IN];     // [w*64+n][k]  (W transposed)
__device__ __nv_bfloat16 g_wl[192 * D_IN];
__device__ __half        g_qf[M_TOT * H_SZ];   // q, single fp16, PRE-SCALED
__device__ __half        g_kf[M_TOT * H_SZ];   // k, single fp16
__device__ __half        g_vt[B_SZ][H_SZ][T_SEQ];   // V transposed, single fp16
// split-KV partials
__device__ float g_po[NSPLIT][M_TOT][H_SZ];    // unnormalized O
__device__ float g_pm[NSPLIT][M_TOT];          // running max (log2 domain)
__device__ float g_pl[NSPLIT][M_TOT];          // running sum

// ---------------- helpers ----------------
__device__ __forceinline__ void mma_bf16(float d[4], const uint32_t a[4],
                                         const uint32_t b[2]) {
    asm("mma.sync.aligned.m16n8k16.row.col.f32.bf16.bf16.f32 "
        "{%0,%1,%2,%3}, {%4,%5,%6,%7}, {%8,%9}, {%0,%1,%2,%3};\n"
        : "+f"(d[0]), "+f"(d[1]), "+f"(d[2]), "+f"(d[3])
        : "r"(a[0]), "r"(a[1]), "r"(a[2]), "r"(a[3]), "r"(b[0]), "r"(b[1]));
}

__device__ __forceinline__ void mma_fp16(float d[4], const uint32_t a[4],
                                         const uint32_t b[2]) {
    asm("mma.sync.aligned.m16n8k16.row.col.f32.f16.f16.f32 "
        "{%0,%1,%2,%3}, {%4,%5,%6,%7}, {%8,%9}, {%0,%1,%2,%3};\n"
        : "+f"(d[0]), "+f"(d[1]), "+f"(d[2]), "+f"(d[3])
        : "r"(a[0]), "r"(a[1]), "r"(a[2]), "r"(a[3]), "r"(b[0]), "r"(b[1]));
}

__device__ __forceinline__ void ldsm4(uint32_t r[4], uint32_t addr) {
    asm volatile("ldmatrix.sync.aligned.m8n8.x4.shared.b16 {%0,%1,%2,%3}, [%4];"
        : "=r"(r[0]), "=r"(r[1]), "=r"(r[2]), "=r"(r[3]) : "r"(addr));
}

__device__ __forceinline__ uint32_t pack2bf(float v0, float v1) {
    uint32_t r;
    asm("cvt.rn.bf16x2.f32 %0, %1, %2;" : "=r"(r) : "f"(v1), "f"(v0));
    return r;
}

// hi/lo split using packed bf16x2 cvt + bit tricks.
__device__ __forceinline__ void split_pair(float x, float y,
                                           uint32_t& hi, uint32_t& lo) {
    hi = pack2bf(x, y);
    const float hx = __uint_as_float(hi << 16);
    const float hy = __uint_as_float(hi & 0xFFFF0000u);
    lo = pack2bf(x - hx, y - hy);
}

__device__ __forceinline__ uint32_t pack2h(float v0, float v1) {
    __half2 h = __floats2half2_rn(v0, v1);
    return *(uint32_t*)&h;
}

__device__ __forceinline__ float ex2f(float x) {
    float r;
    asm("ex2.approx.ftz.f32 %0, %1;" : "=f"(r) : "f"(x));
    return r;
}

#define CP_ASYNC16(dst, src) \
    asm volatile("cp.async.cg.shared.global [%0], [%1], 16;" \
                 :: "r"(dst), "l"(src) : "memory")
#define CP_COMMIT() asm volatile("cp.async.commit_group;" ::: "memory")
#define CP_WAIT1()  asm volatile("cp.async.wait_group 1;" ::: "memory")
#define CP_WAIT0()  asm volatile("cp.async.wait_group 0;" ::: "memory")

#define SCALE_L2E 0.18033688f   // 64^-0.5 * log2(e)

// ---------------------------------------------------------------------------
// transpose + split W
// ---------------------------------------------------------------------------
__global__ __launch_bounds__(256) void split_w_kernel(
    const float* __restrict__ Wq, const float* __restrict__ Wk,
    const float* __restrict__ Wv)
{
    const int idx = blockIdx.x * 256 + threadIdx.x;
    const int w = idx >> 16;
    const int n = (idx >> 10) & 63;
    const int k = idx & 1023;
    const float* W = (w == 0) ? Wq : ((w == 1) ? Wk : Wv);
    const float val = W[k * 64 + n];
    __nv_bfloat16 h = __float2bfloat16(val);
    g_wh[idx] = h;
    g_wl[idx] = __float2bfloat16(val - __bfloat162float(h));
}

// ---------------------------------------------------------------------------
// QKV projection, K-CHUNK=64, 3-stage pipeline (R15). Epilogue: q/k single
// fp16 (q pre-scaled), v fp16 transposed.
// ---------------------------------------------------------------------------
#define QS_XL    9216
#define QS_WH    18432
#define QS_WL    46080
#define QS_STAGE 73728
#define KCHUNK   64
#define NCHUNK   16
#define QSTAGES  3

__global__ __launch_bounds__(256) void qkv_mma_kernel(const float* __restrict__ x)
{
    extern __shared__ __align__(16) char qsm[];
    const uint32_t smbase = (uint32_t)__cvta_generic_to_shared(qsm);

    const int tid  = threadIdx.x;
    const int lane = tid & 31;
    const int wid  = tid >> 5;
    const int wm = wid & 1, wn = wid >> 1;
    const int lq = lane >> 2;
    const int lc = (lane & 3) * 2;
    const int m0 = blockIdx.x * 64;

    const int lm = lane >> 3;
    const int lr = lane & 7;
    const uint32_t arowcol = (uint32_t)(((lm & 1) * 8 + lr) * 144 + (lm >> 1) * 16);
    const uint32_t browcol = (uint32_t)(((lm >> 1) * 8 + lr) * 144 + (lm & 1) * 16);

    const int xrr = tid >> 2;
    const int xuu = tid & 3;

    #define QPREF_W(stage, c_)                                                 \
    do {                                                                       \
        const uint32_t st = smbase + (stage) * QS_STAGE;                       \
        const int k0 = (c_) * KCHUNK;                                          \
        _Pragma("unroll")                                                      \
        for (int p = 0; p < 6; p++) {                                          \
            const int idx = tid + p * 256;                                     \
            const int r = idx >> 3, u = idx & 7;                               \
            CP_ASYNC16(st + QS_WH + r * 144 + u * 16,                          \
                       &g_wh[r * D_IN + k0 + u * 8]);                          \
            CP_ASYNC16(st + QS_WL + r * 144 + u * 16,                          \
                       &g_wl[r * D_IN + k0 + u * 8]);                          \
        }                                                                      \
    } while (0)

    float d[2][6][4];
    #pragma unroll
    for (int mf = 0; mf < 2; mf++)
        #pragma unroll
        for (int j = 0; j < 6; j++)
            #pragma unroll
            for (int r = 0; r < 4; r++) d[mf][j][r] = 0.0f;

    float4 xr[4];
    #pragma unroll
    for (int p = 0; p < 4; p++)
        xr[p] = *(const float4*)&x[(m0 + xrr) * D_IN + (xuu + p * 4) * 4];
    QPREF_W(0, 0);
    CP_COMMIT();
    QPREF_W(1, 1);
    CP_COMMIT();

    int sidx = 0;
    for (int c = 0; c < NCHUNK; c++) {
        const uint32_t stb = smbase + sidx * QS_STAGE;
        __nv_bfloat16* xs_h = (__nv_bfloat16*)(qsm + sidx * QS_STAGE);
        __nv_bfloat16* xs_l = (__nv_bfloat16*)(qsm + sidx * QS_STAGE + QS_XL);
        const uint32_t xsh_s = stb;
        const uint32_t xsl_s = stb + QS_XL;
        const uint32_t wsh_s = stb + QS_WH;
        const uint32_t wsl_s = stb + QS_WL;

        #pragma unroll
        for (int p = 0; p < 4; p++) {
            uint32_t hi01, lo01, hi23, lo23;
            split_pair(xr[p].x, xr[p].y, hi01, lo01);
            split_pair(xr[p].z, xr[p].w, hi23, lo23);
            const int e = (xuu + p * 4) * 4;
            *(uint2*)&xs_h[xrr * 72 + e] = make_uint2(hi01, hi23);
            *(uint2*)&xs_l[xrr * 72 + e] = make_uint2(lo01, lo23);
        }
        if (c + 1 < NCHUNK) {
            const int k0n = (c + 1) * KCHUNK;
            #pragma unroll
            for (int p = 0; p < 4; p++)
                xr[p] = *(const float4*)&x[(m0 + xrr) * D_IN + k0n + (xuu + p * 4) * 4];
        }
        if (c + 1 < NCHUNK) CP_WAIT1(); else CP_WAIT0();
        __syncthreads();
        if (c + 2 < NCHUNK) {
            const int s2 = (sidx + 2 >= QSTAGES) ? sidx - 1 : sidx + 2;
            QPREF_W(s2, c + 2);
            CP_COMMIT();
        }

        #pragma unroll
        for (int kc = 0; kc < 4; kc++) {
            uint32_t ah[2][4], al[2][4];
            #pragma unroll
            for (int mf = 0; mf < 2; mf++) {
                const uint32_t ro = (uint32_t)((wm * 32 + mf * 16) * 144 + kc * 32);
                ldsm4(ah[mf], xsh_s + ro + arowcol);
                ldsm4(al[mf], xsl_s + ro + arowcol);
            }
            #pragma unroll
            for (int jp = 0; jp < 3; jp++) {
                const uint32_t ro = (uint32_t)((wn * 48 + jp * 16) * 144 + kc * 32);
                uint32_t bh[4], bl[4];
                ldsm4(bh, wsh_s + ro + browcol);
                ldsm4(bl, wsl_s + ro + browcol);
                #pragma unroll
                for (int mf = 0; mf < 2; mf++) {
                    mma_bf16(d[mf][2 * jp],     ah[mf], bh);
                    mma_bf16(d[mf][2 * jp],     ah[mf], bl);
                    mma_bf16(d[mf][2 * jp],     al[mf], bh);
                    mma_bf16(d[mf][2 * jp + 1], ah[mf], bh + 2);
                    mma_bf16(d[mf][2 * jp + 1], ah[mf], bl + 2);
                    mma_bf16(d[mf][2 * jp + 1], al[mf], bh + 2);
                }
            }
        }
        __syncthreads();
        sidx = (sidx + 1 == QSTAGES) ? 0 : sidx + 1;
    }

    // epilogue: q/k single fp16; v fp16 transposed
    #pragma unroll
    for (int mf = 0; mf < 2; mf++) {
        #pragma unroll
        for (int j = 0; j < 6; j++) {
            const int col = wn * 48 + j * 8 + lc;
            const int mat = col >> 6;
            const int h   = col & 63;
            #pragma unroll
            for (int half = 0; half < 2; half++) {
                const int row = m0 + wm * 32 + mf * 16 + lq + half * 8;
                float v0 = d[mf][j][half * 2 + 0];
                float v1 = d[mf][j][half * 2 + 1];
                if (mat == 0) {
                    *(uint32_t*)&g_qf[row * 64 + h] =
                        pack2h(v0 * SCALE_L2E, v1 * SCALE_L2E);
                } else if (mat == 1) {
                    *(uint32_t*)&g_kf[row * 64 + h] = pack2h(v0, v1);
                } else {
                    const int b = row >> 11, t = row & 2047;
                    g_vt[b][h][t]     = __float2half(v0);
                    g_vt[b][h + 1][t] = __float2half(v1);
                }
            }
        }
    }
}

// ---------------------------------------------------------------------------
// FA2-style split-KV flash attention. Q/K/V/P all single fp16 (S logits keep
// fp32 accum). GEMM1 = 1 MMA product. Stage = K|V fp16 = 18432 B, 2 stages.
// ---------------------------------------------------------------------------
#define STAGE_BYTES 18432
#define ARR_BYTES   9216        // 64*72*2

__global__ __launch_bounds__(128, 3) void attn_kernel()
{
    const int qt = (QTILES - 1) - blockIdx.x;   // longest-first
    const int ntile = qt + 1;
    const int sp = blockIdx.z;
    const int t0 = sp * TILES_PER_SPLIT;
    if (t0 >= ntile) return;
    const int t1 = min(t0 + TILES_PER_SPLIT, ntile);

    extern __shared__ __align__(16) char smbuf[];
    const uint32_t smbase = (uint32_t)__cvta_generic_to_shared(smbuf);

    const int tid  = threadIdx.x;
    const int lane = tid & 31;
    const int warp = tid >> 5;
    const int lq = lane >> 2;
    const int lc = (lane & 3) * 2;
    const int lm = lane >> 3;
    const int lr = lane & 7;
    const uint32_t browcol = (uint32_t)(((lm >> 1) * 8 + lr) * 144 + (lm & 1) * 16);

    const int b  = blockIdx.y;
    const int q_base = qt * 64;
    const int boff = b * T_SEQ * 64;
    const __half* qbf = g_qf + boff;
    const __half* kbf = g_kf + boff;

    // Q tile via stage-0 smem (fp16), extract frags, release
    {
        __half* Qs = (__half*)(smbuf);
        #pragma unroll
        for (int p = 0; p < 4; p++) {
            const int idx = tid + p * 128;
            const int r = idx >> 3, u = idx & 7;
            *(uint4*)&Qs[r * 72 + u * 8] =
                *(const uint4*)&qbf[(q_base + r) * 64 + u * 8];
        }
    }
    __syncthreads();
    uint32_t qa[4][4];
    {
        const uint32_t arowcol = (uint32_t)(((lm & 1) * 8 + lr) * 144 + (lm >> 1) * 16);
        const uint32_t ro = (uint32_t)(warp * 16 * 144);
        #pragma unroll
        for (int kc = 0; kc < 4; kc++)
            ldsm4(qa[kc], smbase + ro + kc * 32 + arowcol);
    }
    __syncthreads();

    #define PREFETCH(stage, kb_)                                                 \
    do {                                                                         \
        const uint32_t stoff = smbase + (stage) * STAGE_BYTES;                   \
        _Pragma("unroll")                                                        \
        for (int p = 0; p < 4; p++) {                                            \
            const int idx = tid + p * 128;                                       \
            const int r = idx >> 3, u = idx & 7;                                 \
            const uint32_t o = stoff + r * 144 + u * 16;                         \
            CP_ASYNC16(o,             &kbf[((kb_) + r) * 64 + u * 8]);           \
            CP_ASYNC16(o + ARR_BYTES, &g_vt[b][r][(kb_) + u * 8]);               \
        }                                                                        \
    } while (0)

    PREFETCH(0, t0 * 64);
    CP_COMMIT();

    float of[8][4];
    #pragma unroll
    for (int j = 0; j < 8; j++)
        #pragma unroll
        for (int r = 0; r < 4; r++) of[j][r] = 0.0f;
    float m2[2] = {-1e30f, -1e30f};
    float lsum[2] = {0.0f, 0.0f};

    int buf = 0;
    for (int t = t0; t < t1; t++) {
        const int kb = t * 64;
        const bool more = (t + 1 < t1);
        if (more) { PREFETCH(buf ^ 1, (t + 1) * 64); CP_COMMIT(); }
        if (more) CP_WAIT1(); else CP_WAIT0();
        __syncthreads();

        const uint32_t kh_s = smbase + buf * STAGE_BYTES;
        const uint32_t vh_s = kh_s + ARR_BYTES;

        // GEMM1: S = Q K^T — single fp16 product
        float s[8][4];
        #pragma unroll
        for (int j = 0; j < 8; j++)
            #pragma unroll
            for (int r = 0; r < 4; r++) s[j][r] = 0.0f;
        #pragma unroll
        for (int kc = 0; kc < 4; kc++) {
            #pragma unroll
            for (int jp = 0; jp < 4; jp++) {
                uint32_t bh[4];
                ldsm4(bh, kh_s + (uint32_t)(jp * 2304 + kc * 32) + browcol);
                mma_fp16(s[2 * jp],     qa[kc], bh);
                mma_fp16(s[2 * jp + 1], qa[kc], bh + 2);
            }
        }

        if (t == qt) {
            #pragma unroll
            for (int j = 0; j < 8; j++) {
                const int col = kb + j * 8 + lc;
                #pragma unroll
                for (int half = 0; half < 2; half++) {
                    const int qrow = q_base + warp * 16 + lq + half * 8;
                    s[j][half * 2 + 0] = (col     <= qrow) ? s[j][half * 2 + 0] : -1e30f;
                    s[j][half * 2 + 1] = (col + 1 <= qrow) ? s[j][half * 2 + 1] : -1e30f;
                }
            }
        }

        float pm[2] = {-1e30f, -1e30f};
        #pragma unroll
        for (int j = 0; j < 8; j++) {
            pm[0] = fmaxf(pm[0], fmaxf(s[j][0], s[j][1]));
            pm[1] = fmaxf(pm[1], fmaxf(s[j][2], s[j][3]));
        }
        pm[0] = fmaxf(pm[0], __shfl_xor_sync(0xffffffffu, pm[0], 1));
        pm[1] = fmaxf(pm[1], __shfl_xor_sync(0xffffffffu, pm[1], 1));
        pm[0] = fmaxf(pm[0], __shfl_xor_sync(0xffffffffu, pm[0], 2));
        pm[1] = fmaxf(pm[1], __shfl_xor_sync(0xffffffffu, pm[1], 2));

        float mnew[2], alpha[2];
        #pragma unroll
        for (int half = 0; half < 2; half++) {
            mnew[half]  = fmaxf(m2[half], pm[half]);
            alpha[half] = ex2f(m2[half] - mnew[half]);
            m2[half]    = mnew[half];
        }
        float ps[2] = {0.0f, 0.0f};
        #pragma unroll
        for (int j = 0; j < 8; j++) {
            s[j][0] = ex2f(s[j][0] - mnew[0]);
            s[j][1] = ex2f(s[j][1] - mnew[0]);
            s[j][2] = ex2f(s[j][2] - mnew[1]);
            s[j][3] = ex2f(s[j][3] - mnew[1]);
            ps[0] += s[j][0] + s[j][1];
            ps[1] += s[j][2] + s[j][3];
        }
        ps[0] += __shfl_xor_sync(0xffffffffu, ps[0], 1);
        ps[1] += __shfl_xor_sync(0xffffffffu, ps[1], 1);
        ps[0] += __shfl_xor_sync(0xffffffffu, ps[0], 2);
        ps[1] += __shfl_xor_sync(0xffffffffu, ps[1], 2);

        lsum[0] = lsum[0] * alpha[0] + ps[0];
        lsum[1] = lsum[1] * alpha[1] + ps[1];
        #pragma unroll
        for (int j = 0; j < 8; j++) {
            of[j][0] *= alpha[0]; of[j][1] *= alpha[0];
            of[j][2] *= alpha[1]; of[j][3] *= alpha[1];
        }

        // GEMM2: O += P V — single fp16 product
        #pragma unroll
        for (int kc = 0; kc < 4; kc++) {
            uint32_t ap[4];
            ap[0] = pack2h(s[2 * kc][0],     s[2 * kc][1]);
            ap[1] = pack2h(s[2 * kc][2],     s[2 * kc][3]);
            ap[2] = pack2h(s[2 * kc + 1][0], s[2 * kc + 1][1]);
            ap[3] = pack2h(s[2 * kc + 1][2], s[2 * kc + 1][3]);
            #pragma unroll
            for (int jp = 0; jp < 4; jp++) {
                uint32_t bv[4];
                ldsm4(bv, vh_s + (uint32_t)(jp * 2304 + kc * 32) + browcol);
                mma_fp16(of[2 * jp],     ap, bv);
                mma_fp16(of[2 * jp + 1], ap, bv + 2);
            }
        }
        __syncthreads();
        buf ^= 1;
    }

    const int rowg = b * T_SEQ + q_base + warp * 16 + lq;
    #pragma unroll
    for (int j = 0; j < 8; j++) {
        const int col = j * 8 + lc;
        *(float2*)&g_po[sp][rowg][col]     = make_float2(of[j][0], of[j][1]);
        *(float2*)&g_po[sp][rowg + 8][col] = make_float2(of[j][2], of[j][3]);
    }
    if ((lane & 3) == 0) {
        g_pm[sp][rowg]     = m2[0];
        g_pm[sp][rowg + 8] = m2[1];
        g_pl[sp][rowg]     = lsum[0];
        g_pl[sp][rowg + 8] = lsum[1];
    }
}

// ---------------------------------------------------------------------------
// Combine partial splits (NSPLIT=6).
// ---------------------------------------------------------------------------
__global__ __launch_bounds__(128) void combine_kernel(float* __restrict__ out)
{
    const int idx = blockIdx.x * 128 + threadIdx.x;
    const int r = idx >> 4;
    const int c = (idx & 15) * 4;
    const int rr = r & (T_SEQ - 1);
    const int qt = rr >> 6;
    const int nsplit = ((qt + 1) + TILES_PER_SPLIT - 1) / TILES_PER_SPLIT;

    float pm[NSPLIT];
    float M = -1e30f;
    #pragma unroll
    for (int s = 0; s < NSPLIT; s++) {
        pm[s] = (s < nsplit) ? g_pm[s][r] : -1e30f;
        M = fmaxf(M, pm[s]);
    }
    float L = 0.0f;
    float4 acc = make_float4(0.0f, 0.0f, 0.0f, 0.0f);
    #pragma unroll
    for (int s = 0; s < NSPLIT; s++) {
        if (s < nsplit) {
            const float w = ex2f(pm[s] - M);
            L += w * g_pl[s][r];
            float4 o = *(const float4*)&g_po[s][r][c];
            acc.x += w * o.x; acc.y += w * o.y;
            acc.z += w * o.z; acc.w += w * o.w;
        }
    }
    const float inv = 1.0f / L;
    acc.x *= inv; acc.y *= inv; acc.z *= inv; acc.w *= inv;
    *(float4*)&out[r * 64 + c] = acc;
}

extern "C" void kernel_launch(void* const* d_in, const int* in_sizes, int n_in,
                              void* d_out, int out_size)
{
    const float* x  = (const float*)d_in[0];
    const float* Wq = (const float*)d_in[1];
    const float* Wk = (const float*)d_in[2];
    const float* Wv = (const float*)d_in[3];
    float* out = (float*)d_out;

    cudaFuncSetAttribute(attn_kernel,
                         cudaFuncAttributeMaxDynamicSharedMemorySize,
                         2 * STAGE_BYTES);
    cudaFuncSetAttribute(qkv_mma_kernel,
                         cudaFuncAttributeMaxDynamicSharedMemorySize,
                         QSTAGES * QS_STAGE);

    split_w_kernel<<<3 * 64 * 1024 / 256, 256>>>(Wq, Wk, Wv);
    qkv_mma_kernel<<<M_TOT / 64, 256, QSTAGES * QS_STAGE>>>(x);
    attn_kernel<<<dim3(QTILES, B_SZ, NSPLIT), 128, 2 * STAGE_BYTES>>>();
    combine_kernel<<<M_TOT * H_SZ / 512, 128>>>(out);
}

// round 17
// speedup vs baseline: 1.4773x; 1.4773x over previous
#include <cuda_runtime.h>
#include <cuda_bf16.h>
#include <cuda_fp16.h>
#include <cstdint>

#define D_IN 1024
#define H_SZ 64
#define M_TOT 8192   // B*T
#define T_SEQ 2048
#define B_SZ 4
#define NSPLIT 6
#define TILES_PER_SPLIT 6
#define QTILES 32            // T_SEQ / 64

// ---------------- global scratch ----------------
__device__ __nv_bfloat16 g_wh[192 * D_IN];     // [w*64+n][k]  (W transposed)
__device__ __nv_bfloat16 g_wl[192 * D_IN];
__device__ __half        g_qf[M_TOT * H_SZ];   // q, single fp16, PRE-SCALED
__device__ __half        g_kf[M_TOT * H_SZ];   // k, single fp16
__device__ __half        g_vt[B_SZ][H_SZ][T_SEQ];   // V transposed, single fp16
// split-KV partials
__device__ float g_po[NSPLIT][M_TOT][H_SZ];    // unnormalized O
__device__ float g_pm[NSPLIT][M_TOT];          // running max (log2 domain)
__device__ float g_pl[NSPLIT][M_TOT];          // running sum

// ---------------- helpers ----------------
__device__ __forceinline__ void mma_bf16(float d[4], const uint32_t a[4],
                                         const uint32_t b[2]) {
    asm("mma.sync.aligned.m16n8k16.row.col.f32.bf16.bf16.f32 "
        "{%0,%1,%2,%3}, {%4,%5,%6,%7}, {%8,%9}, {%0,%1,%2,%3};\n"
        : "+f"(d[0]), "+f"(d[1]), "+f"(d[2]), "+f"(d[3])
        : "r"(a[0]), "r"(a[1]), "r"(a[2]), "r"(a[3]), "r"(b[0]), "r"(b[1]));
}

__device__ __forceinline__ void mma_fp16(float d[4], const uint32_t a[4],
                                         const uint32_t b[2]) {
    asm("mma.sync.aligned.m16n8k16.row.col.f32.f16.f16.f32 "
        "{%0,%1,%2,%3}, {%4,%5,%6,%7}, {%8,%9}, {%0,%1,%2,%3};\n"
        : "+f"(d[0]), "+f"(d[1]), "+f"(d[2]), "+f"(d[3])
        : "r"(a[0]), "r"(a[1]), "r"(a[2]), "r"(a[3]), "r"(b[0]), "r"(b[1]));
}

__device__ __forceinline__ void ldsm4(uint32_t r[4], uint32_t addr) {
    asm volatile("ldmatrix.sync.aligned.m8n8.x4.shared.b16 {%0,%1,%2,%3}, [%4];"
        : "=r"(r[0]), "=r"(r[1]), "=r"(r[2]), "=r"(r[3]) : "r"(addr));
}

__device__ __forceinline__ uint32_t pack2bf(float v0, float v1) {
    uint32_t r;
    asm("cvt.rn.bf16x2.f32 %0, %1, %2;" : "=r"(r) : "f"(v1), "f"(v0));
    return r;
}

// hi/lo split using packed bf16x2 cvt + bit tricks.
__device__ __forceinline__ void split_pair(float x, float y,
                                           uint32_t& hi, uint32_t& lo) {
    hi = pack2bf(x, y);
    const float hx = __uint_as_float(hi << 16);
    const float hy = __uint_as_float(hi & 0xFFFF0000u);
    lo = pack2bf(x - hx, y - hy);
}

__device__ __forceinline__ uint32_t pack2h(float v0, float v1) {
    __half2 h = __floats2half2_rn(v0, v1);
    return *(uint32_t*)&h;
}

__device__ __forceinline__ float ex2f(float x) {
    float r;
    asm("ex2.approx.ftz.f32 %0, %1;" : "=f"(r) : "f"(x));
    return r;
}

#define CP_ASYNC16(dst, src) \
    asm volatile("cp.async.cg.shared.global [%0], [%1], 16;" \
                 :: "r"(dst), "l"(src) : "memory")
#define CP_COMMIT() asm volatile("cp.async.commit_group;" ::: "memory")
#define CP_WAIT1()  asm volatile("cp.async.wait_group 1;" ::: "memory")
#define CP_WAIT0()  asm volatile("cp.async.wait_group 0;" ::: "memory")

#define SCALE_L2E 0.18033688f   // 64^-0.5 * log2(e)

// ---------------------------------------------------------------------------
// transpose + split W
// ---------------------------------------------------------------------------
__global__ __launch_bounds__(256) void split_w_kernel(
    const float* __restrict__ Wq, const float* __restrict__ Wk,
    const float* __restrict__ Wv)
{
    const int idx = blockIdx.x * 256 + threadIdx.x;
    const int w = idx >> 16;
    const int n = (idx >> 10) & 63;
    const int k = idx & 1023;
    const float* W = (w == 0) ? Wq : ((w == 1) ? Wk : Wv);
    const float val = W[k * 64 + n];
    __nv_bfloat16 h = __float2bfloat16(val);
    g_wh[idx] = h;
    g_wl[idx] = __float2bfloat16(val - __bfloat162float(h));
}

// ---------------------------------------------------------------------------
// QKV projection, K-CHUNK=64, 3-stage pipeline (R15). Epilogue: q/k single
// fp16 (q pre-scaled), v fp16 transposed.
// ---------------------------------------------------------------------------
#define QS_XL    9216
#define QS_WH    18432
#define QS_WL    46080
#define QS_STAGE 73728
#define KCHUNK   64
#define NCHUNK   16
#define QSTAGES  3

__global__ __launch_bounds__(256) void qkv_mma_kernel(const float* __restrict__ x)
{
    extern __shared__ __align__(16) char qsm[];
    const uint32_t smbase = (uint32_t)__cvta_generic_to_shared(qsm);

    const int tid  = threadIdx.x;
    const int lane = tid & 31;
    const int wid  = tid >> 5;
    const int wm = wid & 1, wn = wid >> 1;
    const int lq = lane >> 2;
    const int lc = (lane & 3) * 2;
    const int m0 = blockIdx.x * 64;

    const int lm = lane >> 3;
    const int lr = lane & 7;
    const uint32_t arowcol = (uint32_t)(((lm & 1) * 8 + lr) * 144 + (lm >> 1) * 16);
    const uint32_t browcol = (uint32_t)(((lm >> 1) * 8 + lr) * 144 + (lm & 1) * 16);

    const int xrr = tid >> 2;
    const int xuu = tid & 3;

    #define QPREF_W(stage, c_)                                                 \
    do {                                                                       \
        const uint32_t st = smbase + (stage) * QS_STAGE;                       \
        const int k0 = (c_) * KCHUNK;                                          \
        _Pragma("unroll")                                                      \
        for (int p = 0; p < 6; p++) {                                          \
            const int idx = tid + p * 256;                                     \
            const int r = idx >> 3, u = idx & 7;                               \
            CP_ASYNC16(st + QS_WH + r * 144 + u * 16,                          \
                       &g_wh[r * D_IN + k0 + u * 8]);                          \
            CP_ASYNC16(st + QS_WL + r * 144 + u * 16,                          \
                       &g_wl[r * D_IN + k0 + u * 8]);                          \
        }                                                                      \
    } while (0)

    float d[2][6][4];
    #pragma unroll
    for (int mf = 0; mf < 2; mf++)
        #pragma unroll
        for (int j = 0; j < 6; j++)
            #pragma unroll
            for (int r = 0; r < 4; r++) d[mf][j][r] = 0.0f;

    float4 xr[4];
    #pragma unroll
    for (int p = 0; p < 4; p++)
        xr[p] = *(const float4*)&x[(m0 + xrr) * D_IN + (xuu + p * 4) * 4];
    QPREF_W(0, 0);
    CP_COMMIT();
    QPREF_W(1, 1);
    CP_COMMIT();

    int sidx = 0;
    for (int c = 0; c < NCHUNK; c++) {
        const uint32_t stb = smbase + sidx * QS_STAGE;
        __nv_bfloat16* xs_h = (__nv_bfloat16*)(qsm + sidx * QS_STAGE);
        __nv_bfloat16* xs_l = (__nv_bfloat16*)(qsm + sidx * QS_STAGE + QS_XL);
        const uint32_t xsh_s = stb;
        const uint32_t xsl_s = stb + QS_XL;
        const uint32_t wsh_s = stb + QS_WH;
        const uint32_t wsl_s = stb + QS_WL;

        #pragma unroll
        for (int p = 0; p < 4; p++) {
            uint32_t hi01, lo01, hi23, lo23;
            split_pair(xr[p].x, xr[p].y, hi01, lo01);
            split_pair(xr[p].z, xr[p].w, hi23, lo23);
            const int e = (xuu + p * 4) * 4;
            *(uint2*)&xs_h[xrr * 72 + e] = make_uint2(hi01, hi23);
            *(uint2*)&xs_l[xrr * 72 + e] = make_uint2(lo01, lo23);
        }
        if (c + 1 < NCHUNK) {
            const int k0n = (c + 1) * KCHUNK;
            #pragma unroll
            for (int p = 0; p < 4; p++)
                xr[p] = *(const float4*)&x[(m0 + xrr) * D_IN + k0n + (xuu + p * 4) * 4];
        }
        if (c + 1 < NCHUNK) CP_WAIT1(); else CP_WAIT0();
        __syncthreads();
        if (c + 2 < NCHUNK) {
            const int s2 = (sidx + 2 >= QSTAGES) ? sidx - 1 : sidx + 2;
            QPREF_W(s2, c + 2);
            CP_COMMIT();
        }

        #pragma unroll
        for (int kc = 0; kc < 4; kc++) {
            uint32_t ah[2][4], al[2][4];
            #pragma unroll
            for (int mf = 0; mf < 2; mf++) {
                const uint32_t ro = (uint32_t)((wm * 32 + mf * 16) * 144 + kc * 32);
                ldsm4(ah[mf], xsh_s + ro + arowcol);
                ldsm4(al[mf], xsl_s + ro + arowcol);
            }
            #pragma unroll
            for (int jp = 0; jp < 3; jp++) {
                const uint32_t ro = (uint32_t)((wn * 48 + jp * 16) * 144 + kc * 32);
                uint32_t bh[4], bl[4];
                ldsm4(bh, wsh_s + ro + browcol);
                ldsm4(bl, wsl_s + ro + browcol);
                #pragma unroll
                for (int mf = 0; mf < 2; mf++) {
                    mma_bf16(d[mf][2 * jp],     ah[mf], bh);
                    mma_bf16(d[mf][2 * jp],     ah[mf], bl);
                    mma_bf16(d[mf][2 * jp],     al[mf], bh);
                    mma_bf16(d[mf][2 * jp + 1], ah[mf], bh + 2);
                    mma_bf16(d[mf][2 * jp + 1], ah[mf], bl + 2);
                    mma_bf16(d[mf][2 * jp + 1], al[mf], bh + 2);
                }
            }
        }
        __syncthreads();
        sidx = (sidx + 1 == QSTAGES) ? 0 : sidx + 1;
    }

    // epilogue: q/k single fp16; v fp16 transposed
    #pragma unroll
    for (int mf = 0; mf < 2; mf++) {
        #pragma unroll
        for (int j = 0; j < 6; j++) {
            const int col = wn * 48 + j * 8 + lc;
            const int mat = col >> 6;
            const int h   = col & 63;
            #pragma unroll
            for (int half = 0; half < 2; half++) {
                const int row = m0 + wm * 32 + mf * 16 + lq + half * 8;
                float v0 = d[mf][j][half * 2 + 0];
                float v1 = d[mf][j][half * 2 + 1];
                if (mat == 0) {
                    *(uint32_t*)&g_qf[row * 64 + h] =
                        pack2h(v0 * SCALE_L2E, v1 * SCALE_L2E);
                } else if (mat == 1) {
                    *(uint32_t*)&g_kf[row * 64 + h] = pack2h(v0, v1);
                } else {
                    const int b = row >> 11, t = row & 2047;
                    g_vt[b][h][t]     = __float2half(v0);
                    g_vt[b][h + 1][t] = __float2half(v1);
                }
            }
        }
    }
}

// ---------------------------------------------------------------------------
// FA2-style split-KV flash attention, fp16 single-product GEMMs (R16 compute)
// with R15's STAGE GEOMETRY: stage padded to 27648 B so the smem footprint /
// CTA co-residency (<=4/SM) matches the proven 62.0us configuration.
// Stage layout: Kf[64][72] fp16 | Vf[64][72] fp16 | 9216 B pad.
// ---------------------------------------------------------------------------
#define STAGE_BYTES 27648
#define ARR_BYTES   9216        // 64*72*2

__global__ __launch_bounds__(128, 3) void attn_kernel()
{
    const int qt = (QTILES - 1) - blockIdx.x;   // longest-first
    const int ntile = qt + 1;
    const int sp = blockIdx.z;
    const int t0 = sp * TILES_PER_SPLIT;
    if (t0 >= ntile) return;
    const int t1 = min(t0 + TILES_PER_SPLIT, ntile);

    extern __shared__ __align__(16) char smbuf[];
    const uint32_t smbase = (uint32_t)__cvta_generic_to_shared(smbuf);

    const int tid  = threadIdx.x;
    const int lane = tid & 31;
    const int warp = tid >> 5;
    const int lq = lane >> 2;
    const int lc = (lane & 3) * 2;
    const int lm = lane >> 3;
    const int lr = lane & 7;
    const uint32_t browcol = (uint32_t)(((lm >> 1) * 8 + lr) * 144 + (lm & 1) * 16);

    const int b  = blockIdx.y;
    const int q_base = qt * 64;
    const int boff = b * T_SEQ * 64;
    const __half* qbf = g_qf + boff;
    const __half* kbf = g_kf + boff;

    // Q tile via stage-0 smem (fp16), extract frags, release
    {
        __half* Qs = (__half*)(smbuf);
        #pragma unroll
        for (int p = 0; p < 4; p++) {
            const int idx = tid + p * 128;
            const int r = idx >> 3, u = idx & 7;
            *(uint4*)&Qs[r * 72 + u * 8] =
                *(const uint4*)&qbf[(q_base + r) * 64 + u * 8];
        }
    }
    __syncthreads();
    uint32_t qa[4][4];
    {
        const uint32_t arowcol = (uint32_t)(((lm & 1) * 8 + lr) * 144 + (lm >> 1) * 16);
        const uint32_t ro = (uint32_t)(warp * 16 * 144);
        #pragma unroll
        for (int kc = 0; kc < 4; kc++)
            ldsm4(qa[kc], smbase + ro + kc * 32 + arowcol);
    }
    __syncthreads();

    #define PREFETCH(stage, kb_)                                                 \
    do {                                                                         \
        const uint32_t stoff = smbase + (stage) * STAGE_BYTES;                   \
        _Pragma("unroll")                                                        \
        for (int p = 0; p < 4; p++) {                                            \
            const int idx = tid + p * 128;                                       \
            const int r = idx >> 3, u = idx & 7;                                 \
            const uint32_t o = stoff + r * 144 + u * 16;                         \
            CP_ASYNC16(o,             &kbf[((kb_) + r) * 64 + u * 8]);           \
            CP_ASYNC16(o + ARR_BYTES, &g_vt[b][r][(kb_) + u * 8]);               \
        }                                                                        \
    } while (0)

    PREFETCH(0, t0 * 64);
    CP_COMMIT();

    float of[8][4];
    #pragma unroll
    for (int j = 0; j < 8; j++)
        #pragma unroll
        for (int r = 0; r < 4; r++) of[j][r] = 0.0f;
    float m2[2] = {-1e30f, -1e30f};
    float lsum[2] = {0.0f, 0.0f};

    int buf = 0;
    for (int t = t0; t < t1; t++) {
        const int kb = t * 64;
        const bool more = (t + 1 < t1);
        if (more) { PREFETCH(buf ^ 1, (t + 1) * 64); CP_COMMIT(); }
        if (more) CP_WAIT1(); else CP_WAIT0();
        __syncthreads();

        const uint32_t kh_s = smbase + buf * STAGE_BYTES;
        const uint32_t vh_s = kh_s + ARR_BYTES;

        // GEMM1: S = Q K^T — single fp16 product
        float s[8][4];
        #pragma unroll
        for (int j = 0; j < 8; j++)
            #pragma unroll
            for (int r = 0; r < 4; r++) s[j][r] = 0.0f;
        #pragma unroll
        for (int kc = 0; kc < 4; kc++) {
            #pragma unroll
            for (int jp = 0; jp < 4; jp++) {
                uint32_t bh[4];
                ldsm4(bh, kh_s + (uint32_t)(jp * 2304 + kc * 32) + browcol);
                mma_fp16(s[2 * jp],     qa[kc], bh);
                mma_fp16(s[2 * jp + 1], qa[kc], bh + 2);
            }
        }

        if (t == qt) {
            #pragma unroll
            for (int j = 0; j < 8; j++) {
                const int col = kb + j * 8 + lc;
                #pragma unroll
                for (int half = 0; half < 2; half++) {
                    const int qrow = q_base + warp * 16 + lq + half * 8;
                    s[j][half * 2 + 0] = (col     <= qrow) ? s[j][half * 2 + 0] : -1e30f;
                    s[j][half * 2 + 1] = (col + 1 <= qrow) ? s[j][half * 2 + 1] : -1e30f;
                }
            }
        }

        float pm[2] = {-1e30f, -1e30f};
        #pragma unroll
        for (int j = 0; j < 8; j++) {
            pm[0] = fmaxf(pm[0], fmaxf(s[j][0], s[j][1]));
            pm[1] = fmaxf(pm[1], fmaxf(s[j][2], s[j][3]));
        }
        pm[0] = fmaxf(pm[0], __shfl_xor_sync(0xffffffffu, pm[0], 1));
        pm[1] = fmaxf(pm[1], __shfl_xor_sync(0xffffffffu, pm[1], 1));
        pm[0] = fmaxf(pm[0], __shfl_xor_sync(0xffffffffu, pm[0], 2));
        pm[1] = fmaxf(pm[1], __shfl_xor_sync(0xffffffffu, pm[1], 2));

        float mnew[2], alpha[2];
        #pragma unroll
        for (int half = 0; half < 2; half++) {
            mnew[half]  = fmaxf(m2[half], pm[half]);
            alpha[half] = ex2f(m2[half] - mnew[half]);
            m2[half]    = mnew[half];
        }
        float ps[2] = {0.0f, 0.0f};
        #pragma unroll
        for (int j = 0; j < 8; j++) {
            s[j][0] = ex2f(s[j][0] - mnew[0]);
            s[j][1] = ex2f(s[j][1] - mnew[0]);
            s[j][2] = ex2f(s[j][2] - mnew[1]);
            s[j][3] = ex2f(s[j][3] - mnew[1]);
            ps[0] += s[j][0] + s[j][1];
            ps[1] += s[j][2] + s[j][3];
        }
        ps[0] += __shfl_xor_sync(0xffffffffu, ps[0], 1);
        ps[1] += __shfl_xor_sync(0xffffffffu, ps[1], 1);
        ps[0] += __shfl_xor_sync(0xffffffffu, ps[0], 2);
        ps[1] += __shfl_xor_sync(0xffffffffu, ps[1], 2);

        lsum[0] = lsum[0] * alpha[0] + ps[0];
        lsum[1] = lsum[1] * alpha[1] + ps[1];
        #pragma unroll
        for (int j = 0; j < 8; j++) {
            of[j][0] *= alpha[0]; of[j][1] *= alpha[0];
            of[j][2] *= alpha[1]; of[j][3] *= alpha[1];
        }

        // GEMM2: O += P V — single fp16 product
        #pragma unroll
        for (int kc = 0; kc < 4; kc++) {
            uint32_t ap[4];
            ap[0] = pack2h(s[2 * kc][0],     s[2 * kc][1]);
            ap[1] = pack2h(s[2 * kc][2],     s[2 * kc][3]);
            ap[2] = pack2h(s[2 * kc + 1][0], s[2 * kc + 1][1]);
            ap[3] = pack2h(s[2 * kc + 1][2], s[2 * kc + 1][3]);
            #pragma unroll
            for (int jp = 0; jp < 4; jp++) {
                uint32_t bv[4];
                ldsm4(bv, vh_s + (uint32_t)(jp * 2304 + kc * 32) + browcol);
                mma_fp16(of[2 * jp],     ap, bv);
                mma_fp16(of[2 * jp + 1], ap, bv + 2);
            }
        }
        __syncthreads();
        buf ^= 1;
    }

    const int rowg = b * T_SEQ + q_base + warp * 16 + lq;
    #pragma unroll
    for (int j = 0; j < 8; j++) {
        const int col = j * 8 + lc;
        *(float2*)&g_po[sp][rowg][col]     = make_float2(of[j][0], of[j][1]);
        *(float2*)&g_po[sp][rowg + 8][col] = make_float2(of[j][2], of[j][3]);
    }
    if ((lane & 3) == 0) {
        g_pm[sp][rowg]     = m2[0];
        g_pm[sp][rowg + 8] = m2[1];
        g_pl[sp][rowg]     = lsum[0];
        g_pl[sp][rowg + 8] = lsum[1];
    }
}

// ---------------------------------------------------------------------------
// Combine partial splits (NSPLIT=6).
// ---------------------------------------------------------------------------
__global__ __launch_bounds__(128) void combine_kernel(float* __restrict__ out)
{
    const int idx = blockIdx.x * 128 + threadIdx.x;
    const int r = idx >> 4;
    const int c = (idx & 15) * 4;
    const int rr = r & (T_SEQ - 1);
    const int qt = rr >> 6;
    const int nsplit = ((qt + 1) + TILES_PER_SPLIT - 1) / TILES_PER_SPLIT;

    float pm[NSPLIT];
    float M = -1e30f;
    #pragma unroll
    for (int s = 0; s < NSPLIT; s++) {
        pm[s] = (s < nsplit) ? g_pm[s][r] : -1e30f;
        M = fmaxf(M, pm[s]);
    }
    float L = 0.0f;
    float4 acc = make_float4(0.0f, 0.0f, 0.0f, 0.0f);
    #pragma unroll
    for (int s = 0; s < NSPLIT; s++) {
        if (s < nsplit) {
            const float w = ex2f(pm[s] - M);
            L += w * g_pl[s][r];
            float4 o = *(const float4*)&g_po[s][r][c];
            acc.x += w * o.x; acc.y += w * o.y;
            acc.z += w * o.z; acc.w += w * o.w;
        }
    }
    const float inv = 1.0f / L;
    acc.x *= inv; acc.y *= inv; acc.z *= inv; acc.w *= inv;
    *(float4*)&out[r * 64 + c] = acc;
}

extern "C" void kernel_launch(void* const* d_in, const int* in_sizes, int n_in,
                              void* d_out, int out_size)
{
    const float* x  = (const float*)d_in[0];
    const float* Wq = (const float*)d_in[1];
    const float* Wk = (const float*)d_in[2];
    const float* Wv = (const float*)d_in[3];
    float* out = (float*)d_out;

    cudaFuncSetAttribute(attn_kernel,
                         cudaFuncAttributeMaxDynamicSharedMemorySize,
                         2 * STAGE_BYTES);
    cudaFuncSetAttribute(qkv_mma_kernel,
                         cudaFuncAttributeMaxDynamicSharedMemorySize,
                         QSTAGES * QS_STAGE);

    split_w_kernel<<<3 * 64 * 1024 / 256, 256>>>(Wq, Wk, Wv);
    qkv_mma_kernel<<<M_TOT / 64, 256, QSTAGES * QS_STAGE>>>(x);
    attn_kernel<<<dim3(QTILES, B_SZ, NSPLIT), 128, 2 * STAGE_BYTES>>>();
    combine_kernel<<<M_TOT * H_SZ / 512, 128>>>(out);
}